// round 15
// baseline (speedup 1.0000x reference)
#include <cuda_runtime.h>
#include <cuda_bf16.h>
#include <cuda_fp16.h>
#include <cstdint>

#define SQ 2048
#define NB 2
#define NH 16
#define DKH 64
#define DM 1024
#define NBH (NB * NH)

static const size_t XN = (size_t)NB * SQ * DM;    // 4,194,304
static const size_t WN = (size_t)DM * DM;         // 1,048,576
#define AN ((size_t)NBH * SQ * SQ)                // 134,217,728

// ---------------- device scratch (alloc-free) ----------------
__device__ __half        g_xq[XN], g_xk[XN], g_xv[XN];     // fp16 inputs
__device__ __half        g_wqkv[3 * WN];                   // fp16 weights concat [3072,1024]
__device__ float         g_bqkv[3 * DM];                   // concat bias
__device__ __half        g_wo_hi[WN], g_wo_lo[WN];         // Wo split fp16
__device__ __half        g_qh[XN], g_kh[XN];               // [bh, s, d] fp16
__device__ __half        g_vt[XN];                         // [bh, d, s] fp16
__device__ __half        g_ctx[XN];                        // [b*s, h*d] fp16
__device__ __half        g_pt[AN];                         // p_tile = exp(s - M_tile) fp16
__device__ float2 g_stats[(size_t)NBH * 16 * SQ];          // per-tile (max, sumexp)
__device__ float g_att_scratch[AN];
__device__ float g_dummy_out[XN];

// ---------------- helpers ----------------
template <class A, class B> struct is_same_t { static const bool v = false; };
template <class A> struct is_same_t<A, A> { static const bool v = true; };

__device__ __forceinline__ uint32_t smem_u32(const void* p) {
    uint32_t a;
    asm("{ .reg .u64 t; cvta.to.shared.u64 t, %1; cvt.u32.u64 %0, t; }" : "=r"(a) : "l"(p));
    return a;
}
__device__ __forceinline__ void cpa16(uint32_t s, const void* g) {
    asm volatile("cp.async.ca.shared.global [%0], [%1], 16;" :: "r"(s), "l"(g));
}
__device__ __forceinline__ void cpa_commit() { asm volatile("cp.async.commit_group;"); }
template <int N>
__device__ __forceinline__ void cpa_waitg() {
    asm volatile("cp.async.wait_group %0;" :: "n"(N));
}
__device__ __forceinline__ void ldm4(uint32_t d[4], uint32_t addr) {
    asm volatile("ldmatrix.sync.aligned.m8n8.x4.shared.b16 {%0,%1,%2,%3}, [%4];"
                 : "=r"(d[0]), "=r"(d[1]), "=r"(d[2]), "=r"(d[3]) : "r"(addr));
}
template <bool BF16>
__device__ __forceinline__ void mma16816(float c[4], const uint32_t a[4],
                                         uint32_t b0, uint32_t b1) {
    if (BF16)
        asm volatile(
            "mma.sync.aligned.m16n8k16.row.col.f32.bf16.bf16.f32 "
            "{%0,%1,%2,%3}, {%4,%5,%6,%7}, {%8,%9}, {%0,%1,%2,%3};"
            : "+f"(c[0]), "+f"(c[1]), "+f"(c[2]), "+f"(c[3])
            : "r"(a[0]), "r"(a[1]), "r"(a[2]), "r"(a[3]), "r"(b0), "r"(b1));
    else
        asm volatile(
            "mma.sync.aligned.m16n8k16.row.col.f32.f16.f16.f32 "
            "{%0,%1,%2,%3}, {%4,%5,%6,%7}, {%8,%9}, {%0,%1,%2,%3};"
            : "+f"(c[0]), "+f"(c[1]), "+f"(c[2]), "+f"(c[3])
            : "r"(a[0]), "r"(a[1]), "r"(a[2]), "r"(a[3]), "r"(b0), "r"(b1));
}
__device__ __forceinline__ uint32_t pack_hf2(float v0, float v1) {
    __half2 h = __floats2half2_rn(v0, v1);
    return *(uint32_t*)&h;
}

// ============================================================
// MMA GEMM: C[128 x BN] = A[128 x K] * B[BN x K]^T  (rows stride K)
// SPLIT=1: single mma.  SPLIT=2: B split (hi,lo), 2 mma.
// MAXB: blocks/SM (reg budget).
// MODE 2: out proj -> fp32 [m, DM]  (+bias)
// MODE 3: scores -> p_t fp16 (coalesced via smem stage) + tile stats
// MODE 4: normalize + PV -> att fp32 (stcs) + fp16 ctx
//         (rowstat computed inline from stats)
// MODE 5: merged QKV proj -> q/k fp16 scatter [bh,s,d], v fp16 [bh,d,s]
// ============================================================
template <int BN, int MODE, int SPLIT, int NSTG, int MAXB, typename T>
__global__ __launch_bounds__(256, MAXB)
void mma_gemm(const T* __restrict__ Ah_g, const T* __restrict__ Al_g,
              const void* __restrict__ Aux_g,
              const T* __restrict__ Bh_g, const T* __restrict__ Bl_g,
              const float* __restrict__ bias, const int* __restrict__ mask,
              float* __restrict__ outf, uint32_t* __restrict__ ohi,
              uint32_t* __restrict__ olo, uint32_t* __restrict__ ov,
              float2* __restrict__ stats,
              const T* __restrict__ Ak_g, const T* __restrict__ Av_g,
              int K, size_t sAz, size_t sBz)
{
    constexpr bool BF16 = is_same_t<T, __nv_bfloat16>::v;
    constexpr int BM = 128, BK = 32;
    constexpr int ASZ = BM * 80;
    constexpr int BSZ = BN * 80;
    constexpr int BPART = (SPLIT >= 2) ? 2 : 1;
    constexpr int OFF_BH = ASZ;
    constexpr int STG = ASZ + BSZ * BPART;
    constexpr int NSPAN = BN / 2;
    constexpr int NT = NSPAN / 8;

    extern __shared__ char smem[];
    const uint32_t sb = smem_u32(smem);
    const int tid = threadIdx.x;
    const int lane = tid & 31, wid = tid >> 5;
    const int wm = wid & 3, wn = wid >> 2;

    const int m0 = blockIdx.y * BM;
    const int n0 = blockIdx.x * BN;
    const int z  = blockIdx.z;
    const int sec = (MODE == 5) ? (n0 >> 10) : 0;

    const T* pAh = Ah_g ? Ah_g + (size_t)z * sAz : nullptr;
    if (MODE == 5) pAh = (sec == 0) ? Ah_g : (sec == 1) ? Ak_g : Av_g;
    const __half* pPt = (MODE == 4) ? (const __half*)Aux_g + (size_t)z * sAz : nullptr;
    float* pW = (MODE == 4) ? outf + (size_t)z * sAz : nullptr;
    const T* pBh = Bh_g + (size_t)z * sBz;
    const T* pBl = Bl_g ? Bl_g + (size_t)z * sBz : nullptr;

    const int NCH = K / BK;

    // MODE 4: per-row (max, invS) computed inline from per-tile stats
    float2 rs[4];
    float sc[4];
    int cur_t = -1;
    if (MODE == 4) {
#pragma unroll
        for (int j = 0; j < 4; j++) {
            const int row = m0 + (tid >> 3) + j * 32;
            float M = -1e30f;
            for (int kb = 0; kb < 16; kb++)
                M = fmaxf(M, stats[((size_t)z * 16 + kb) * SQ + row].x);
            float S = 0.0f;
            for (int kb = 0; kb < 16; kb++) {
                const float2 t = stats[((size_t)z * 16 + kb) * SQ + row];
                S += t.y * __expf(t.x - M);
            }
            rs[j] = make_float2(M, 1.0f / S);
        }
    }

    auto issue = [&](int c, int st) {
        const int kb = c * BK;
        const uint32_t base = sb + st * STG;
        if (MODE != 4) {
#pragma unroll
            for (int j = 0; j < 2; j++) {
                int u = tid + j * 256, r = u >> 2, c8 = u & 3;
                cpa16(base + r * 80 + c8 * 16,
                      pAh + (size_t)(m0 + r) * K + kb + c8 * 8);
            }
        }
#pragma unroll
        for (int j = 0; j < (BN == 128 ? 2 : 1); j++) {
            int u = tid + j * 256, r = u >> 2, c8 = u & 3;
            cpa16(base + OFF_BH + r * 80 + c8 * 16,
                  pBh + (size_t)(n0 + r) * K + kb + c8 * 8);
            if (SPLIT >= 2)
                cpa16(base + OFF_BH + BSZ + r * 80 + c8 * 16,
                      pBl + (size_t)(n0 + r) * K + kb + c8 * 8);
        }
    };

    // ----- MODE 4: p_t fp16 loads + scale + att write + fp16 smem store -----
    uint2 rAp[4];
    auto loadA = [&](int c) {
        const int kb = c * BK;
#pragma unroll
        for (int j = 0; j < 4; j++) {
            int u = tid + j * 256, r = u >> 3, c4 = u & 7;
            rAp[j] = *(const uint2*)(pPt + (size_t)(m0 + r) * K + kb + c4 * 4);
        }
    };
    auto storeA = [&](int c) {
        const int st = c % NSTG, kb = c * BK;
        char* base = smem + st * STG;
        const int t = c >> 2;
        if (t != cur_t) {
            cur_t = t;
#pragma unroll
            for (int j = 0; j < 4; j++) {
                const int r = (tid >> 3) + j * 32;
                const float Mt = stats[((size_t)z * 16 + t) * SQ + m0 + r].x;
                sc[j] = __expf(Mt - rs[j].x) * rs[j].y;
            }
        }
#pragma unroll
        for (int j = 0; j < 4; j++) {
            int u = tid + j * 256, r = u >> 3, c4 = u & 7;
            __half2 h01 = *(__half2*)&rAp[j].x;
            __half2 h23 = *(__half2*)&rAp[j].y;
            float4 p;
            p.x = __low2float(h01)  * sc[j];
            p.y = __high2float(h01) * sc[j];
            p.z = __low2float(h23)  * sc[j];
            p.w = __high2float(h23) * sc[j];
            __stcs((float4*)(pW + (size_t)(m0 + r) * K + kb + c4 * 4), p);
            __half2 o0 = __floats2half2_rn(p.x, p.y);
            __half2 o1 = __floats2half2_rn(p.z, p.w);
            *(int2*)(base + r * 80 + c4 * 8) = make_int2(*(int*)&o0, *(int*)&o1);
        }
    };

    float acc[2][NT][4];
#pragma unroll
    for (int a = 0; a < 2; a++)
#pragma unroll
        for (int b = 0; b < NT; b++)
#pragma unroll
            for (int c = 0; c < 4; c++) acc[a][b][c] = 0.0f;

#pragma unroll
    for (int s = 0; s < NSTG - 1; s++) {
        if (s < NCH) issue(s, s);
        cpa_commit();
    }
    if (MODE == 4) { loadA(0); storeA(0); }

    for (int c = 0; c < NCH; c++) {
        const int st = c % NSTG;
        cpa_waitg<NSTG - 2>();
        __syncthreads();
        if (c + NSTG - 1 < NCH) issue(c + NSTG - 1, (c + NSTG - 1) % NSTG);
        cpa_commit();
        if (MODE == 4 && c + 1 < NCH) loadA(c + 1);

        const uint32_t aBase = sb + st * STG;
        const uint32_t bBase = aBase + OFF_BH;
#pragma unroll
        for (int ks = 0; ks < 2; ks++) {
            uint32_t ah[2][4];
#pragma unroll
            for (int mt = 0; mt < 2; mt++) {
                uint32_t ad = aBase + (wm * 32 + mt * 16 + (lane & 15)) * 80
                              + ks * 32 + ((lane >> 4) << 4);
                ldm4(ah[mt], ad);
            }
            const int g = lane >> 3;
            const int nsub = (g >> 1) * 8, khalf = (g & 1) * 16;
#pragma unroll
            for (int ntp = 0; ntp < NT / 2; ntp++) {
                uint32_t bd = bBase
                    + (wn * NSPAN + ntp * 16 + nsub + (lane & 7)) * 80
                    + ks * 32 + khalf;
                uint32_t bh[4];
                ldm4(bh, bd);
#pragma unroll
                for (int mt = 0; mt < 2; mt++) {
                    mma16816<BF16>(acc[mt][2 * ntp],     ah[mt], bh[0], bh[1]);
                    mma16816<BF16>(acc[mt][2 * ntp + 1], ah[mt], bh[2], bh[3]);
                }
                if (SPLIT >= 2) {
                    uint32_t bl[4];
                    ldm4(bl, bd + BSZ);
#pragma unroll
                    for (int mt = 0; mt < 2; mt++) {
                        mma16816<BF16>(acc[mt][2 * ntp],     ah[mt], bl[0], bl[1]);
                        mma16816<BF16>(acc[mt][2 * ntp + 1], ah[mt], bl[2], bl[3]);
                    }
                }
            }
        }
        if (MODE == 4 && c + 1 < NCH) storeA(c + 1);
    }
    __syncthreads();

    // ---------------- epilogue ----------------
    float (*sf)[BN + 1] = (float(*)[BN + 1])smem;  // MODE5-V staging (BN-sized!)

#pragma unroll
    for (int mt = 0; mt < 2; mt++)
#pragma unroll
        for (int nt = 0; nt < NT; nt++)
#pragma unroll
            for (int hh = 0; hh < 2; hh++) {
                float v0 = acc[mt][nt][hh * 2 + 0];
                float v1 = acc[mt][nt][hh * 2 + 1];
                const int m_loc = wm * 32 + mt * 16 + (lane >> 2) + hh * 8;
                const int n_loc = wn * NSPAN + nt * 8 + (lane & 3) * 2;
                const int gm = m0 + m_loc, gn = n0 + n_loc;

                if (MODE == 2) {
                    v0 += bias[gn]; v1 += bias[gn + 1];
                    *(float2*)&outf[(size_t)gm * DM + gn] = make_float2(v0, v1);
                } else if (MODE == 3) {
                    v0 *= 0.125f; v1 *= 0.125f;
                    const size_t midx = ((size_t)(z >> 4) * SQ + gm) * SQ + gn;
                    int2 mv = *(const int2*)(mask + midx);
                    if (mv.x == 0) v0 = 1e-9f;
                    if (mv.y == 0) v1 = 1e-9f;
                    acc[mt][nt][hh * 2 + 0] = v0;
                    acc[mt][nt][hh * 2 + 1] = v1;
                } else if (MODE == 4) {
                    const int b = z >> 4, h = z & 15;
                    const size_t a = (((size_t)(b * SQ + gm)) * DM + h * DKH + gn) >> 1;
                    ohi[a] = pack_hf2(v0, v1);
                } else if (MODE == 5) {
                    v0 += bias[gn]; v1 += bias[gn + 1];
                    if (sec < 2) {
                        const int gnl = gn & 1023;
                        const int b = gm >> 11, s = gm & 2047, h = gnl >> 6, d = gnl & 63;
                        const size_t a = ((((size_t)(b * NH + h)) * SQ + s) * DKH + d) >> 1;
                        (sec ? olo : ohi)[a] = pack_hf2(v0, v1);
                    } else {
                        sf[m_loc][n_loc]     = v0;
                        sf[m_loc][n_loc + 1] = v1;
                    }
                }
            }

    if (MODE == 5 && sec == 2) {                   // V transpose -> [bh, d, s]
        __syncthreads();
        const int b = m0 >> 11, s0 = m0 & 2047;
        const int gnl_base = n0 & 1023;
#pragma unroll
        for (int it = 0; it < BN / 8; it++) {
            const int rn = it * 8 + wid;
            const int gnl = gnl_base + rn;
            const int h = gnl >> 6, d = gnl & 63;
            uint32_t* orow = ov + ((((size_t)(b * NH + h)) * DKH + d) * SQ + s0) / 2;
#pragma unroll
            for (int j = 0; j < 2; j++) {
                const int sp = j * 64 + 2 * lane;
                orow[j * 32 + lane] = pack_hf2(sf[sp][rn], sf[sp + 1][rn]);
            }
        }
    }

    if (MODE == 3) {
        float* smax = (float*)smem;                       // [2][128]
        float* ssum = smax + 256;
        __half (*stg)[136] = (__half(*)[136])(smem + 2048); // 128 x 136 halves
        // phase 1: per-half row max
#pragma unroll
        for (int mt = 0; mt < 2; mt++)
#pragma unroll
            for (int hh = 0; hh < 2; hh++) {
                float mx = -1e30f;
#pragma unroll
                for (int nt = 0; nt < NT; nt++)
                    mx = fmaxf(mx, fmaxf(acc[mt][nt][hh * 2], acc[mt][nt][hh * 2 + 1]));
                mx = fmaxf(mx, __shfl_xor_sync(0xffffffffu, mx, 1));
                mx = fmaxf(mx, __shfl_xor_sync(0xffffffffu, mx, 2));
                if ((lane & 3) == 0)
                    smax[wn * 128 + wm * 32 + mt * 16 + hh * 8 + (lane >> 2)] = mx;
            }
        __syncthreads();
        // phase 2: combined max -> p_t into smem stage + sums
#pragma unroll
        for (int mt = 0; mt < 2; mt++)
#pragma unroll
            for (int hh = 0; hh < 2; hh++) {
                const int m_loc = wm * 32 + mt * 16 + hh * 8 + (lane >> 2);
                const float mx = fmaxf(smax[m_loc], smax[128 + m_loc]);
                float sm = 0.0f;
#pragma unroll
                for (int nt = 0; nt < NT; nt++) {
                    const float e0 = __expf(acc[mt][nt][hh * 2 + 0] - mx);
                    const float e1 = __expf(acc[mt][nt][hh * 2 + 1] - mx);
                    sm += e0 + e1;
                    const int n_loc = wn * NSPAN + nt * 8 + (lane & 3) * 2;
                    *(uint32_t*)&stg[m_loc][n_loc] = pack_hf2(e0, e1);
                }
                sm += __shfl_xor_sync(0xffffffffu, sm, 1);
                sm += __shfl_xor_sync(0xffffffffu, sm, 2);
                if ((lane & 3) == 0) ssum[wn * 128 + m_loc] = sm;
            }
        __syncthreads();
        if (tid < 128) {
            stats[((size_t)z * 16 + blockIdx.x) * SQ + m0 + tid] =
                make_float2(fmaxf(smax[tid], smax[128 + tid]),
                            ssum[tid] + ssum[128 + tid]);
        }
        // coalesced p_t copy: 128 rows x 128 halves, 16B/lane streaming
        __half* pPtOut = (__half*)ohi;
#pragma unroll
        for (int it = 0; it < 8; it++) {
            const int u = tid + it * 256;
            const int r = u >> 4, c8 = u & 15;
            int4 val = *(int4*)&stg[r][c8 * 8];
            __stcs((int4*)(pPtOut + ((size_t)z * SQ + m0 + r) * SQ + n0 + c8 * 8), val);
        }
    }
}

// ---------------- fp32 -> fp16 (3 tensors in one launch) ----------------
__global__ __launch_bounds__(256)
void cvt_half3(const float* __restrict__ x0, const float* __restrict__ x1,
               const float* __restrict__ x2,
               __half* __restrict__ o0, __half* __restrict__ o1,
               __half* __restrict__ o2, size_t n4)
{
    size_t i = (size_t)blockIdx.x * blockDim.x + threadIdx.x;
    const int sel = (int)(i / n4);
    const size_t j = i - (size_t)sel * n4;
    const float* x = (sel == 0) ? x0 : (sel == 1) ? x1 : x2;
    __half* o = (sel == 0) ? o0 : (sel == 1) ? o1 : o2;
    float4 v = ((const float4*)x)[j];
    __half2 h0 = __floats2half2_rn(v.x, v.y);
    __half2 h1 = __floats2half2_rn(v.z, v.w);
    ((int2*)o)[j] = make_int2(*(int*)&h0, *(int*)&h1);
}

// ---------------- Wo fp16 hi/lo split + bias concat (fused) ----------------
__global__ __launch_bounds__(256)
void cvt_wo_bias(const float* __restrict__ Wo, __half* __restrict__ hi,
                 __half* __restrict__ lo,
                 const float* __restrict__ ba, const float* __restrict__ bb,
                 const float* __restrict__ bc, float* __restrict__ bqkv)
{
    const size_t n4 = WN / 4;
    size_t i = (size_t)blockIdx.x * 256 + threadIdx.x;
    if (i < n4) {
        float4 v = ((const float4*)Wo)[i];
        float f[4] = {v.x, v.y, v.z, v.w};
        uint32_t h[4], l[4];
#pragma unroll
        for (int j = 0; j < 4; j++) {
            __half hb = __float2half_rn(f[j]);
            __half lb = __float2half_rn(f[j] - __half2float(hb));
            h[j] = (uint32_t)__half_as_ushort(hb);
            l[j] = (uint32_t)__half_as_ushort(lb);
        }
        ((int2*)hi)[i] = make_int2((int)(h[0] | (h[1] << 16)), (int)(h[2] | (h[3] << 16)));
        ((int2*)lo)[i] = make_int2((int)(l[0] | (l[1] << 16)), (int)(l[2] | (l[3] << 16)));
    } else {
        const int kk = (int)(i - n4);
        if (kk < 3 * DM)
            bqkv[kk] = (kk < DM) ? ba[kk] : (kk < 2 * DM) ? bb[kk - DM] : bc[kk - 2 * DM];
    }
}

// ============================================================
extern "C" void kernel_launch(void* const* d_in, const int* in_sizes, int n_in,
                              void* d_out, int out_size)
{
    const float* q    = (const float*)d_in[0];
    const float* k    = (const float*)d_in[1];
    const float* v    = (const float*)d_in[2];
    const int*   mask = (const int*)  d_in[3];
    const float* Wq   = (const float*)d_in[4];
    const float* bq   = (const float*)d_in[5];
    const float* Wk   = (const float*)d_in[6];
    const float* bk   = (const float*)d_in[7];
    const float* Wv   = (const float*)d_in[8];
    const float* bv   = (const float*)d_in[9];
    const float* Wo   = (const float*)d_in[10];
    const float* bo   = (const float*)d_in[11];

    __half *xq, *xk, *xv, *wqkv, *qh, *kh, *vt, *pt, *ctx, *wo_hi, *wo_lo;
    float *bqkv;
    float *attscr, *dummy;
    float2 *statsp;
    cudaGetSymbolAddress((void**)&xq, g_xq); cudaGetSymbolAddress((void**)&xk, g_xk);
    cudaGetSymbolAddress((void**)&xv, g_xv);
    cudaGetSymbolAddress((void**)&wqkv, g_wqkv);
    cudaGetSymbolAddress((void**)&bqkv, g_bqkv);
    cudaGetSymbolAddress((void**)&wo_hi, g_wo_hi); cudaGetSymbolAddress((void**)&wo_lo, g_wo_lo);
    cudaGetSymbolAddress((void**)&qh, g_qh); cudaGetSymbolAddress((void**)&kh, g_kh);
    cudaGetSymbolAddress((void**)&vt, g_vt);
    cudaGetSymbolAddress((void**)&pt, g_pt);
    cudaGetSymbolAddress((void**)&ctx, g_ctx);
    cudaGetSymbolAddress((void**)&attscr, g_att_scratch);
    cudaGetSymbolAddress((void**)&dummy,  g_dummy_out);
    cudaGetSymbolAddress((void**)&statsp, g_stats);

    const long OUT_ELEMS = (long)NB * SQ * DM;
    const long ATT_ELEMS = (long)AN;
    float* outp = (float*)d_out;
    float* attp;
    if ((long)out_size >= OUT_ELEMS + ATT_ELEMS)      attp = outp + OUT_ELEMS;
    else if ((long)out_size == ATT_ELEMS) { attp = outp; outp = dummy; }
    else                                               attp = attscr;

    constexpr int SM_P1_128 = 3 * (10240 + 10240);          // 61440
    constexpr int SM_PROJ   = 3 * (10240 + 5120);            // 46080 (BN=64; V staging 33280 fits)
    constexpr int SM_PV     = 3 * (10240 + 5120);            // 46080
    constexpr int SM_S2_64  = 3 * (10240 + 2 * 5120);        // 61440

    cudaFuncSetAttribute(mma_gemm<64, 5, 1, 3, 3, __half>,
                         cudaFuncAttributeMaxDynamicSharedMemorySize, SM_PROJ);
    cudaFuncSetAttribute(mma_gemm<128, 3, 1, 3, 2, __half>,
                         cudaFuncAttributeMaxDynamicSharedMemorySize, SM_P1_128);
    cudaFuncSetAttribute(mma_gemm<64, 4, 1, 3, 2, __half>,
                         cudaFuncAttributeMaxDynamicSharedMemorySize, SM_PV);
    cudaFuncSetAttribute(mma_gemm<64, 2, 2, 3, 2, __half>,
                         cudaFuncAttributeMaxDynamicSharedMemorySize, SM_S2_64);

    // conversions
    cvt_half3<<<(int)(3 * XN / 4 / 256), 256>>>(q, k, v, xq, xk, xv, XN / 4);
    cvt_half3<<<(int)(3 * WN / 4 / 256), 256>>>(Wq, Wk, Wv, wqkv, wqkv + WN,
                                                wqkv + 2 * WN, WN / 4);
    cvt_wo_bias<<<(int)(WN / 4 / 256) + 12, 256>>>(Wo, wo_hi, wo_lo, bq, bk, bv, bqkv);

    // merged QKV projection (M=4096, N=3072, K=1024), BN=64, 3 CTAs/SM
    mma_gemm<64, 5, 1, 3, 3, __half><<<dim3(48, 32, 1), 256, SM_PROJ>>>(
        xq, nullptr, nullptr, wqkv, nullptr, bqkv, nullptr, nullptr,
        (uint32_t*)qh, (uint32_t*)kh, (uint32_t*)vt, nullptr,
        xk, xv, DM, 0, 0);

    // scores: p_t fp16 (coalesced) + per-tile row stats
    mma_gemm<128, 3, 1, 3, 2, __half><<<dim3(16, 16, NBH), 256, SM_P1_128>>>(
        qh, nullptr, nullptr, kh, nullptr, nullptr, mask, nullptr,
        (uint32_t*)pt, nullptr, nullptr, statsp,
        nullptr, nullptr, DKH, (size_t)SQ * DKH, (size_t)SQ * DKH);

    // normalize + PV: reads p_t + stats (rowstat inline), writes att fp32 + fp16 ctx
    mma_gemm<64, 4, 1, 3, 2, __half><<<dim3(1, 16, NBH), 256, SM_PV>>>(
        nullptr, nullptr, pt, vt, nullptr, nullptr, nullptr, attp,
        (uint32_t*)ctx, nullptr, nullptr, statsp,
        nullptr, nullptr, SQ, (size_t)SQ * SQ, (size_t)DKH * SQ);

    // output projection: fp16 ctx single x fp16 Wo split-2, BN=64 (512 blocks)
    mma_gemm<64, 2, 2, 3, 2, __half><<<dim3(16, 32, 1), 256, SM_S2_64>>>(
        ctx, nullptr, nullptr, wo_hi, wo_lo, bo, nullptr, outp,
        nullptr, nullptr, nullptr, nullptr,
        nullptr, nullptr, DM, 0, 0);
}

// round 16
// speedup vs baseline: 1.0458x; 1.0458x over previous
#include <cuda_runtime.h>
#include <cuda_bf16.h>
#include <cuda_fp16.h>
#include <cstdint>

#define SQ 2048
#define NB 2
#define NH 16
#define DKH 64
#define DM 1024
#define NBH (NB * NH)

static const size_t XN = (size_t)NB * SQ * DM;    // 4,194,304
static const size_t WN = (size_t)DM * DM;         // 1,048,576
#define AN ((size_t)NBH * SQ * SQ)                // 134,217,728

// ---------------- device scratch (alloc-free) ----------------
__device__ __half        g_xq[XN], g_xk[XN], g_xv[XN];     // fp16 inputs
__device__ __half        g_wqkv[3 * WN];                   // fp16 weights concat [3072,1024]
__device__ float         g_bqkv[3 * DM];                   // concat bias
__device__ __half        g_wo_hi[WN], g_wo_lo[WN];         // Wo split fp16
__device__ __half        g_qh[XN], g_kh[XN];               // [bh, s, d] fp16
__device__ __half        g_vt[XN];                         // [bh, d, s] fp16
__device__ __half        g_ctx[XN];                        // [b*s, h*d] fp16
__device__ __half        g_pt[AN];                         // p_tile = exp(s - M_tile) fp16
__device__ float2 g_stats[(size_t)NBH * 16 * SQ];          // per-tile (max, sumexp)
__device__ float g_att_scratch[AN];
__device__ float g_dummy_out[XN];

// ---------------- helpers ----------------
template <class A, class B> struct is_same_t { static const bool v = false; };
template <class A> struct is_same_t<A, A> { static const bool v = true; };

__device__ __forceinline__ uint32_t smem_u32(const void* p) {
    uint32_t a;
    asm("{ .reg .u64 t; cvta.to.shared.u64 t, %1; cvt.u32.u64 %0, t; }" : "=r"(a) : "l"(p));
    return a;
}
__device__ __forceinline__ void cpa16(uint32_t s, const void* g) {
    asm volatile("cp.async.ca.shared.global [%0], [%1], 16;" :: "r"(s), "l"(g));
}
__device__ __forceinline__ void cpa_commit() { asm volatile("cp.async.commit_group;"); }
template <int N>
__device__ __forceinline__ void cpa_waitg() {
    asm volatile("cp.async.wait_group %0;" :: "n"(N));
}
__device__ __forceinline__ void ldm4(uint32_t d[4], uint32_t addr) {
    asm volatile("ldmatrix.sync.aligned.m8n8.x4.shared.b16 {%0,%1,%2,%3}, [%4];"
                 : "=r"(d[0]), "=r"(d[1]), "=r"(d[2]), "=r"(d[3]) : "r"(addr));
}
template <bool BF16>
__device__ __forceinline__ void mma16816(float c[4], const uint32_t a[4],
                                         uint32_t b0, uint32_t b1) {
    if (BF16)
        asm volatile(
            "mma.sync.aligned.m16n8k16.row.col.f32.bf16.bf16.f32 "
            "{%0,%1,%2,%3}, {%4,%5,%6,%7}, {%8,%9}, {%0,%1,%2,%3};"
            : "+f"(c[0]), "+f"(c[1]), "+f"(c[2]), "+f"(c[3])
            : "r"(a[0]), "r"(a[1]), "r"(a[2]), "r"(a[3]), "r"(b0), "r"(b1));
    else
        asm volatile(
            "mma.sync.aligned.m16n8k16.row.col.f32.f16.f16.f32 "
            "{%0,%1,%2,%3}, {%4,%5,%6,%7}, {%8,%9}, {%0,%1,%2,%3};"
            : "+f"(c[0]), "+f"(c[1]), "+f"(c[2]), "+f"(c[3])
            : "r"(a[0]), "r"(a[1]), "r"(a[2]), "r"(a[3]), "r"(b0), "r"(b1));
}
__device__ __forceinline__ uint32_t pack_hf2(float v0, float v1) {
    __half2 h = __floats2half2_rn(v0, v1);
    return *(uint32_t*)&h;
}

// ============================================================
// MMA GEMM: C[128 x BN] = A[128 x K] * B[BN x K]^T  (rows stride K)
// SPLIT=1: single mma.  SPLIT=2: B split (hi,lo), 2 mma.
// MAXB: blocks/SM (reg budget).
// MODE 2: out proj -> fp32 [m, DM]  (+bias)
// MODE 3: scores -> p_t fp16 (coalesced via smem stage) + tile stats
// MODE 4: normalize + PV -> att fp32 (stcs) + fp16 ctx
//         (rowstat computed inline from stats)
// MODE 5: merged QKV proj -> q/k fp16 scatter [bh,s,d], v fp16 [bh,d,s]
// ============================================================
template <int BN, int MODE, int SPLIT, int NSTG, int MAXB, typename T>
__global__ __launch_bounds__(256, MAXB)
void mma_gemm(const T* __restrict__ Ah_g, const T* __restrict__ Al_g,
              const void* __restrict__ Aux_g,
              const T* __restrict__ Bh_g, const T* __restrict__ Bl_g,
              const float* __restrict__ bias, const int* __restrict__ mask,
              float* __restrict__ outf, uint32_t* __restrict__ ohi,
              uint32_t* __restrict__ olo, uint32_t* __restrict__ ov,
              float2* __restrict__ stats,
              const T* __restrict__ Ak_g, const T* __restrict__ Av_g,
              int K, size_t sAz, size_t sBz)
{
    constexpr bool BF16 = is_same_t<T, __nv_bfloat16>::v;
    constexpr int BM = 128, BK = 32;
    constexpr int ASZ = BM * 80;
    constexpr int BSZ = BN * 80;
    constexpr int BPART = (SPLIT >= 2) ? 2 : 1;
    constexpr int OFF_BH = ASZ;
    constexpr int STG = ASZ + BSZ * BPART;
    constexpr int NSPAN = BN / 2;
    constexpr int NT = NSPAN / 8;

    extern __shared__ char smem[];
    const uint32_t sb = smem_u32(smem);
    const int tid = threadIdx.x;
    const int lane = tid & 31, wid = tid >> 5;
    const int wm = wid & 3, wn = wid >> 2;

    const int m0 = blockIdx.y * BM;
    const int n0 = blockIdx.x * BN;
    const int z  = blockIdx.z;
    const int sec = (MODE == 5) ? (n0 >> 10) : 0;

    const T* pAh = Ah_g ? Ah_g + (size_t)z * sAz : nullptr;
    if (MODE == 5) pAh = (sec == 0) ? Ah_g : (sec == 1) ? Ak_g : Av_g;
    const __half* pPt = (MODE == 4) ? (const __half*)Aux_g + (size_t)z * sAz : nullptr;
    float* pW = (MODE == 4) ? outf + (size_t)z * sAz : nullptr;
    const T* pBh = Bh_g + (size_t)z * sBz;
    const T* pBl = Bl_g ? Bl_g + (size_t)z * sBz : nullptr;

    const int NCH = K / BK;

    // MODE 4: per-row (max, invS) computed inline from per-tile stats
    float2 rs[4];
    float sc[4];
    int cur_t = -1;
    if (MODE == 4) {
#pragma unroll
        for (int j = 0; j < 4; j++) {
            const int row = m0 + (tid >> 3) + j * 32;
            float M = -1e30f;
            for (int kb = 0; kb < 16; kb++)
                M = fmaxf(M, stats[((size_t)z * 16 + kb) * SQ + row].x);
            float S = 0.0f;
            for (int kb = 0; kb < 16; kb++) {
                const float2 t = stats[((size_t)z * 16 + kb) * SQ + row];
                S += t.y * __expf(t.x - M);
            }
            rs[j] = make_float2(M, 1.0f / S);
        }
    }

    auto issue = [&](int c, int st) {
        const int kb = c * BK;
        const uint32_t base = sb + st * STG;
        if (MODE != 4) {
#pragma unroll
            for (int j = 0; j < 2; j++) {
                int u = tid + j * 256, r = u >> 2, c8 = u & 3;
                cpa16(base + r * 80 + c8 * 16,
                      pAh + (size_t)(m0 + r) * K + kb + c8 * 8);
            }
        }
#pragma unroll
        for (int j = 0; j < (BN == 128 ? 2 : 1); j++) {
            int u = tid + j * 256, r = u >> 2, c8 = u & 3;
            cpa16(base + OFF_BH + r * 80 + c8 * 16,
                  pBh + (size_t)(n0 + r) * K + kb + c8 * 8);
            if (SPLIT >= 2)
                cpa16(base + OFF_BH + BSZ + r * 80 + c8 * 16,
                      pBl + (size_t)(n0 + r) * K + kb + c8 * 8);
        }
    };

    // ----- MODE 4: p_t fp16 loads + scale + att write + fp16 smem store -----
    uint2 rAp[4];
    auto loadA = [&](int c) {
        const int kb = c * BK;
#pragma unroll
        for (int j = 0; j < 4; j++) {
            int u = tid + j * 256, r = u >> 3, c4 = u & 7;
            rAp[j] = *(const uint2*)(pPt + (size_t)(m0 + r) * K + kb + c4 * 4);
        }
    };
    auto storeA = [&](int c) {
        const int st = c % NSTG, kb = c * BK;
        char* base = smem + st * STG;
        const int t = c >> 2;
        if (t != cur_t) {
            cur_t = t;
#pragma unroll
            for (int j = 0; j < 4; j++) {
                const int r = (tid >> 3) + j * 32;
                const float Mt = stats[((size_t)z * 16 + t) * SQ + m0 + r].x;
                sc[j] = __expf(Mt - rs[j].x) * rs[j].y;
            }
        }
#pragma unroll
        for (int j = 0; j < 4; j++) {
            int u = tid + j * 256, r = u >> 3, c4 = u & 7;
            __half2 h01 = *(__half2*)&rAp[j].x;
            __half2 h23 = *(__half2*)&rAp[j].y;
            float4 p;
            p.x = __low2float(h01)  * sc[j];
            p.y = __high2float(h01) * sc[j];
            p.z = __low2float(h23)  * sc[j];
            p.w = __high2float(h23) * sc[j];
            __stcs((float4*)(pW + (size_t)(m0 + r) * K + kb + c4 * 4), p);
            __half2 o0 = __floats2half2_rn(p.x, p.y);
            __half2 o1 = __floats2half2_rn(p.z, p.w);
            *(int2*)(base + r * 80 + c4 * 8) = make_int2(*(int*)&o0, *(int*)&o1);
        }
    };

    float acc[2][NT][4];
#pragma unroll
    for (int a = 0; a < 2; a++)
#pragma unroll
        for (int b = 0; b < NT; b++)
#pragma unroll
            for (int c = 0; c < 4; c++) acc[a][b][c] = 0.0f;

#pragma unroll
    for (int s = 0; s < NSTG - 1; s++) {
        if (s < NCH) issue(s, s);
        cpa_commit();
    }
    if (MODE == 4) { loadA(0); storeA(0); }

    for (int c = 0; c < NCH; c++) {
        const int st = c % NSTG;
        cpa_waitg<NSTG - 2>();
        __syncthreads();
        if (c + NSTG - 1 < NCH) issue(c + NSTG - 1, (c + NSTG - 1) % NSTG);
        cpa_commit();
        if (MODE == 4 && c + 1 < NCH) loadA(c + 1);

        const uint32_t aBase = sb + st * STG;
        const uint32_t bBase = aBase + OFF_BH;
#pragma unroll
        for (int ks = 0; ks < 2; ks++) {
            uint32_t ah[2][4];
#pragma unroll
            for (int mt = 0; mt < 2; mt++) {
                uint32_t ad = aBase + (wm * 32 + mt * 16 + (lane & 15)) * 80
                              + ks * 32 + ((lane >> 4) << 4);
                ldm4(ah[mt], ad);
            }
            const int g = lane >> 3;
            const int nsub = (g >> 1) * 8, khalf = (g & 1) * 16;
#pragma unroll
            for (int ntp = 0; ntp < NT / 2; ntp++) {
                uint32_t bd = bBase
                    + (wn * NSPAN + ntp * 16 + nsub + (lane & 7)) * 80
                    + ks * 32 + khalf;
                uint32_t bh[4];
                ldm4(bh, bd);
#pragma unroll
                for (int mt = 0; mt < 2; mt++) {
                    mma16816<BF16>(acc[mt][2 * ntp],     ah[mt], bh[0], bh[1]);
                    mma16816<BF16>(acc[mt][2 * ntp + 1], ah[mt], bh[2], bh[3]);
                }
                if (SPLIT >= 2) {
                    uint32_t bl[4];
                    ldm4(bl, bd + BSZ);
#pragma unroll
                    for (int mt = 0; mt < 2; mt++) {
                        mma16816<BF16>(acc[mt][2 * ntp],     ah[mt], bl[0], bl[1]);
                        mma16816<BF16>(acc[mt][2 * ntp + 1], ah[mt], bl[2], bl[3]);
                    }
                }
            }
        }
        if (MODE == 4 && c + 1 < NCH) storeA(c + 1);
    }
    __syncthreads();

    // ---------------- epilogue ----------------
    float (*sf)[BN + 1] = (float(*)[BN + 1])smem;  // MODE5-V staging

#pragma unroll
    for (int mt = 0; mt < 2; mt++)
#pragma unroll
        for (int nt = 0; nt < NT; nt++)
#pragma unroll
            for (int hh = 0; hh < 2; hh++) {
                float v0 = acc[mt][nt][hh * 2 + 0];
                float v1 = acc[mt][nt][hh * 2 + 1];
                const int m_loc = wm * 32 + mt * 16 + (lane >> 2) + hh * 8;
                const int n_loc = wn * NSPAN + nt * 8 + (lane & 3) * 2;
                const int gm = m0 + m_loc, gn = n0 + n_loc;

                if (MODE == 2) {
                    v0 += bias[gn]; v1 += bias[gn + 1];
                    *(float2*)&outf[(size_t)gm * DM + gn] = make_float2(v0, v1);
                } else if (MODE == 3) {
                    v0 *= 0.125f; v1 *= 0.125f;
                    const size_t midx = ((size_t)(z >> 4) * SQ + gm) * SQ + gn;
                    int2 mv = *(const int2*)(mask + midx);
                    if (mv.x == 0) v0 = 1e-9f;
                    if (mv.y == 0) v1 = 1e-9f;
                    acc[mt][nt][hh * 2 + 0] = v0;
                    acc[mt][nt][hh * 2 + 1] = v1;
                } else if (MODE == 4) {
                    const int b = z >> 4, h = z & 15;
                    const size_t a = (((size_t)(b * SQ + gm)) * DM + h * DKH + gn) >> 1;
                    ohi[a] = pack_hf2(v0, v1);
                } else if (MODE == 5) {
                    v0 += bias[gn]; v1 += bias[gn + 1];
                    if (sec < 2) {
                        const int gnl = gn & 1023;
                        const int b = gm >> 11, s = gm & 2047, h = gnl >> 6, d = gnl & 63;
                        const size_t a = ((((size_t)(b * NH + h)) * SQ + s) * DKH + d) >> 1;
                        (sec ? olo : ohi)[a] = pack_hf2(v0, v1);
                    } else {
                        sf[m_loc][n_loc]     = v0;
                        sf[m_loc][n_loc + 1] = v1;
                    }
                }
            }

    if (MODE == 5 && sec == 2) {                   // V transpose -> [bh, d, s]
        __syncthreads();
        const int b = m0 >> 11, s0 = m0 & 2047;
        const int gnl_base = n0 & 1023;
#pragma unroll
        for (int it = 0; it < BN / 8; it++) {
            const int rn = it * 8 + wid;
            const int gnl = gnl_base + rn;
            const int h = gnl >> 6, d = gnl & 63;
            uint32_t* orow = ov + ((((size_t)(b * NH + h)) * DKH + d) * SQ + s0) / 2;
#pragma unroll
            for (int j = 0; j < 2; j++) {
                const int sp = j * 64 + 2 * lane;
                orow[j * 32 + lane] = pack_hf2(sf[sp][rn], sf[sp + 1][rn]);
            }
        }
    }

    if (MODE == 3) {
        float* smax = (float*)smem;                       // [2][128]
        float* ssum = smax + 256;
        __half (*stg)[136] = (__half(*)[136])(smem + 2048); // 128 x 136 halves
        // phase 1: per-half row max
#pragma unroll
        for (int mt = 0; mt < 2; mt++)
#pragma unroll
            for (int hh = 0; hh < 2; hh++) {
                float mx = -1e30f;
#pragma unroll
                for (int nt = 0; nt < NT; nt++)
                    mx = fmaxf(mx, fmaxf(acc[mt][nt][hh * 2], acc[mt][nt][hh * 2 + 1]));
                mx = fmaxf(mx, __shfl_xor_sync(0xffffffffu, mx, 1));
                mx = fmaxf(mx, __shfl_xor_sync(0xffffffffu, mx, 2));
                if ((lane & 3) == 0)
                    smax[wn * 128 + wm * 32 + mt * 16 + hh * 8 + (lane >> 2)] = mx;
            }
        __syncthreads();
        // phase 2: combined max -> p_t into smem stage + sums
#pragma unroll
        for (int mt = 0; mt < 2; mt++)
#pragma unroll
            for (int hh = 0; hh < 2; hh++) {
                const int m_loc = wm * 32 + mt * 16 + hh * 8 + (lane >> 2);
                const float mx = fmaxf(smax[m_loc], smax[128 + m_loc]);
                float sm = 0.0f;
#pragma unroll
                for (int nt = 0; nt < NT; nt++) {
                    const float e0 = __expf(acc[mt][nt][hh * 2 + 0] - mx);
                    const float e1 = __expf(acc[mt][nt][hh * 2 + 1] - mx);
                    sm += e0 + e1;
                    const int n_loc = wn * NSPAN + nt * 8 + (lane & 3) * 2;
                    *(uint32_t*)&stg[m_loc][n_loc] = pack_hf2(e0, e1);
                }
                sm += __shfl_xor_sync(0xffffffffu, sm, 1);
                sm += __shfl_xor_sync(0xffffffffu, sm, 2);
                if ((lane & 3) == 0) ssum[wn * 128 + m_loc] = sm;
            }
        __syncthreads();
        if (tid < 128) {
            stats[((size_t)z * 16 + blockIdx.x) * SQ + m0 + tid] =
                make_float2(fmaxf(smax[tid], smax[128 + tid]),
                            ssum[tid] + ssum[128 + tid]);
        }
        // coalesced p_t copy: 128 rows x 128 halves, 16B/lane streaming
        __half* pPtOut = (__half*)ohi;
#pragma unroll
        for (int it = 0; it < 8; it++) {
            const int u = tid + it * 256;
            const int r = u >> 4, c8 = u & 15;
            int4 val = *(int4*)&stg[r][c8 * 8];
            __stcs((int4*)(pPtOut + ((size_t)z * SQ + m0 + r) * SQ + n0 + c8 * 8), val);
        }
    }
}

// ---------------- fp32 -> fp16 (3 tensors in one launch) ----------------
__global__ __launch_bounds__(256)
void cvt_half3(const float* __restrict__ x0, const float* __restrict__ x1,
               const float* __restrict__ x2,
               __half* __restrict__ o0, __half* __restrict__ o1,
               __half* __restrict__ o2, size_t n4)
{
    size_t i = (size_t)blockIdx.x * blockDim.x + threadIdx.x;
    const int sel = (int)(i / n4);
    const size_t j = i - (size_t)sel * n4;
    const float* x = (sel == 0) ? x0 : (sel == 1) ? x1 : x2;
    __half* o = (sel == 0) ? o0 : (sel == 1) ? o1 : o2;
    float4 v = ((const float4*)x)[j];
    __half2 h0 = __floats2half2_rn(v.x, v.y);
    __half2 h1 = __floats2half2_rn(v.z, v.w);
    ((int2*)o)[j] = make_int2(*(int*)&h0, *(int*)&h1);
}

// ---------------- Wo fp16 hi/lo split + bias concat (fused) ----------------
__global__ __launch_bounds__(256)
void cvt_wo_bias(const float* __restrict__ Wo, __half* __restrict__ hi,
                 __half* __restrict__ lo,
                 const float* __restrict__ ba, const float* __restrict__ bb,
                 const float* __restrict__ bc, float* __restrict__ bqkv)
{
    const size_t n4 = WN / 4;
    size_t i = (size_t)blockIdx.x * 256 + threadIdx.x;
    if (i < n4) {
        float4 v = ((const float4*)Wo)[i];
        float f[4] = {v.x, v.y, v.z, v.w};
        uint32_t h[4], l[4];
#pragma unroll
        for (int j = 0; j < 4; j++) {
            __half hb = __float2half_rn(f[j]);
            __half lb = __float2half_rn(f[j] - __half2float(hb));
            h[j] = (uint32_t)__half_as_ushort(hb);
            l[j] = (uint32_t)__half_as_ushort(lb);
        }
        ((int2*)hi)[i] = make_int2((int)(h[0] | (h[1] << 16)), (int)(h[2] | (h[3] << 16)));
        ((int2*)lo)[i] = make_int2((int)(l[0] | (l[1] << 16)), (int)(l[2] | (l[3] << 16)));
    } else {
        const int kk = (int)(i - n4);
        if (kk < 3 * DM)
            bqkv[kk] = (kk < DM) ? ba[kk] : (kk < 2 * DM) ? bb[kk - DM] : bc[kk - 2 * DM];
    }
}

// ============================================================
extern "C" void kernel_launch(void* const* d_in, const int* in_sizes, int n_in,
                              void* d_out, int out_size)
{
    const float* q    = (const float*)d_in[0];
    const float* k    = (const float*)d_in[1];
    const float* v    = (const float*)d_in[2];
    const int*   mask = (const int*)  d_in[3];
    const float* Wq   = (const float*)d_in[4];
    const float* bq   = (const float*)d_in[5];
    const float* Wk   = (const float*)d_in[6];
    const float* bk   = (const float*)d_in[7];
    const float* Wv   = (const float*)d_in[8];
    const float* bv   = (const float*)d_in[9];
    const float* Wo   = (const float*)d_in[10];
    const float* bo   = (const float*)d_in[11];

    __half *xq, *xk, *xv, *wqkv, *qh, *kh, *vt, *pt, *ctx, *wo_hi, *wo_lo;
    float *bqkv;
    float *attscr, *dummy;
    float2 *statsp;
    cudaGetSymbolAddress((void**)&xq, g_xq); cudaGetSymbolAddress((void**)&xk, g_xk);
    cudaGetSymbolAddress((void**)&xv, g_xv);
    cudaGetSymbolAddress((void**)&wqkv, g_wqkv);
    cudaGetSymbolAddress((void**)&bqkv, g_bqkv);
    cudaGetSymbolAddress((void**)&wo_hi, g_wo_hi); cudaGetSymbolAddress((void**)&wo_lo, g_wo_lo);
    cudaGetSymbolAddress((void**)&qh, g_qh); cudaGetSymbolAddress((void**)&kh, g_kh);
    cudaGetSymbolAddress((void**)&vt, g_vt);
    cudaGetSymbolAddress((void**)&pt, g_pt);
    cudaGetSymbolAddress((void**)&ctx, g_ctx);
    cudaGetSymbolAddress((void**)&attscr, g_att_scratch);
    cudaGetSymbolAddress((void**)&dummy,  g_dummy_out);
    cudaGetSymbolAddress((void**)&statsp, g_stats);

    const long OUT_ELEMS = (long)NB * SQ * DM;
    const long ATT_ELEMS = (long)AN;
    float* outp = (float*)d_out;
    float* attp;
    if ((long)out_size >= OUT_ELEMS + ATT_ELEMS)      attp = outp + OUT_ELEMS;
    else if ((long)out_size == ATT_ELEMS) { attp = outp; outp = dummy; }
    else                                               attp = attscr;

    constexpr int SM_P1_128 = 3 * (10240 + 10240);          // 61440
    constexpr int SM_PROJ   = 66048;                         // max(61440, 128*129*4 staging)
    constexpr int SM_PV4    = 4 * (10240 + 5120);            // 61440 (4-stage PV)
    constexpr int SM_S2_128 = 3 * (10240 + 2 * 10240);       // 92160

    cudaFuncSetAttribute(mma_gemm<128, 5, 1, 3, 2, __half>,
                         cudaFuncAttributeMaxDynamicSharedMemorySize, SM_PROJ);
    cudaFuncSetAttribute(mma_gemm<128, 3, 1, 3, 2, __half>,
                         cudaFuncAttributeMaxDynamicSharedMemorySize, SM_P1_128);
    cudaFuncSetAttribute(mma_gemm<64, 4, 1, 4, 2, __half>,
                         cudaFuncAttributeMaxDynamicSharedMemorySize, SM_PV4);
    cudaFuncSetAttribute(mma_gemm<128, 2, 2, 3, 2, __half>,
                         cudaFuncAttributeMaxDynamicSharedMemorySize, SM_S2_128);

    // conversions
    cvt_half3<<<(int)(3 * XN / 4 / 256), 256>>>(q, k, v, xq, xk, xv, XN / 4);
    cvt_half3<<<(int)(3 * WN / 4 / 256), 256>>>(Wq, Wk, Wv, wqkv, wqkv + WN,
                                                wqkv + 2 * WN, WN / 4);
    cvt_wo_bias<<<(int)(WN / 4 / 256) + 12, 256>>>(Wo, wo_hi, wo_lo, bq, bk, bv, bqkv);

    // merged QKV projection (M=4096, N=3072, K=1024), BN=128, 2 CTAs/SM
    mma_gemm<128, 5, 1, 3, 2, __half><<<dim3(24, 32, 1), 256, SM_PROJ>>>(
        xq, nullptr, nullptr, wqkv, nullptr, bqkv, nullptr, nullptr,
        (uint32_t*)qh, (uint32_t*)kh, (uint32_t*)vt, nullptr,
        xk, xv, DM, 0, 0);

    // scores: p_t fp16 (coalesced) + per-tile row stats
    mma_gemm<128, 3, 1, 3, 2, __half><<<dim3(16, 16, NBH), 256, SM_P1_128>>>(
        qh, nullptr, nullptr, kh, nullptr, nullptr, mask, nullptr,
        (uint32_t*)pt, nullptr, nullptr, statsp,
        nullptr, nullptr, DKH, (size_t)SQ * DKH, (size_t)SQ * DKH);

    // normalize + PV: 4-stage pipeline (more outstanding loads, no reg change)
    mma_gemm<64, 4, 1, 4, 2, __half><<<dim3(1, 16, NBH), 256, SM_PV4>>>(
        nullptr, nullptr, pt, vt, nullptr, nullptr, nullptr, attp,
        (uint32_t*)ctx, nullptr, nullptr, statsp,
        nullptr, nullptr, SQ, (size_t)SQ * SQ, (size_t)DKH * SQ);

    // output projection: fp16 ctx single x fp16 Wo split-2, BN=128 (champion cfg)
    mma_gemm<128, 2, 2, 3, 2, __half><<<dim3(8, 32, 1), 256, SM_S2_128>>>(
        ctx, nullptr, nullptr, wo_hi, wo_lo, bo, nullptr, outp,
        nullptr, nullptr, nullptr, nullptr,
        nullptr, nullptr, DM, 0, 0);
}

// round 17
// speedup vs baseline: 1.1026x; 1.0543x over previous
#include <cuda_runtime.h>
#include <cuda_bf16.h>
#include <cuda_fp16.h>
#include <cstdint>

#define SQ 2048
#define NB 2
#define NH 16
#define DKH 64
#define DM 1024
#define NBH (NB * NH)

static const size_t XN = (size_t)NB * SQ * DM;    // 4,194,304
static const size_t WN = (size_t)DM * DM;         // 1,048,576
#define AN ((size_t)NBH * SQ * SQ)                // 134,217,728

// ---------------- device scratch (alloc-free) ----------------
__device__ __half        g_xq[XN], g_xk[XN], g_xv[XN];     // fp16 inputs
__device__ __half        g_wqkv[3 * WN];                   // fp16 weights concat [3072,1024]
__device__ float         g_bqkv[3 * DM];                   // concat bias
__device__ __half        g_wo[WN];                         // Wo fp16 (single)
__device__ __half        g_qh[XN], g_kh[XN];               // [bh, s, d] fp16
__device__ __half        g_vt[XN];                         // [bh, d, s] fp16
__device__ __half        g_ctx[XN];                        // [b*s, h*d] fp16
__device__ __half        g_pt[AN];                         // p_tile = exp(s - M_tile) fp16
__device__ float2 g_stats[(size_t)NBH * 16 * SQ];          // per-tile (max, sumexp)
__device__ float g_att_scratch[AN];
__device__ float g_dummy_out[XN];

// ---------------- helpers ----------------
template <class A, class B> struct is_same_t { static const bool v = false; };
template <class A> struct is_same_t<A, A> { static const bool v = true; };

__device__ __forceinline__ uint32_t smem_u32(const void* p) {
    uint32_t a;
    asm("{ .reg .u64 t; cvta.to.shared.u64 t, %1; cvt.u32.u64 %0, t; }" : "=r"(a) : "l"(p));
    return a;
}
__device__ __forceinline__ void cpa16(uint32_t s, const void* g) {
    asm volatile("cp.async.ca.shared.global [%0], [%1], 16;" :: "r"(s), "l"(g));
}
__device__ __forceinline__ void cpa_commit() { asm volatile("cp.async.commit_group;"); }
template <int N>
__device__ __forceinline__ void cpa_waitg() {
    asm volatile("cp.async.wait_group %0;" :: "n"(N));
}
__device__ __forceinline__ void ldm4(uint32_t d[4], uint32_t addr) {
    asm volatile("ldmatrix.sync.aligned.m8n8.x4.shared.b16 {%0,%1,%2,%3}, [%4];"
                 : "=r"(d[0]), "=r"(d[1]), "=r"(d[2]), "=r"(d[3]) : "r"(addr));
}
template <bool BF16>
__device__ __forceinline__ void mma16816(float c[4], const uint32_t a[4],
                                         uint32_t b0, uint32_t b1) {
    if (BF16)
        asm volatile(
            "mma.sync.aligned.m16n8k16.row.col.f32.bf16.bf16.f32 "
            "{%0,%1,%2,%3}, {%4,%5,%6,%7}, {%8,%9}, {%0,%1,%2,%3};"
            : "+f"(c[0]), "+f"(c[1]), "+f"(c[2]), "+f"(c[3])
            : "r"(a[0]), "r"(a[1]), "r"(a[2]), "r"(a[3]), "r"(b0), "r"(b1));
    else
        asm volatile(
            "mma.sync.aligned.m16n8k16.row.col.f32.f16.f16.f32 "
            "{%0,%1,%2,%3}, {%4,%5,%6,%7}, {%8,%9}, {%0,%1,%2,%3};"
            : "+f"(c[0]), "+f"(c[1]), "+f"(c[2]), "+f"(c[3])
            : "r"(a[0]), "r"(a[1]), "r"(a[2]), "r"(a[3]), "r"(b0), "r"(b1));
}
__device__ __forceinline__ uint32_t pack_hf2(float v0, float v1) {
    __half2 h = __floats2half2_rn(v0, v1);
    return *(uint32_t*)&h;
}

// ============================================================
// MMA GEMM: C[128 x BN] = A[128 x K] * B[BN x K]^T  (rows stride K)
// SPLIT=1: single mma.  SPLIT=2: B split (hi,lo), 2 mma.
// MAXB: blocks/SM (reg budget).  NSTG: cp.async pipeline depth.
// MODE 2: out proj -> fp32 [m, DM]  (+bias)
// MODE 3: scores -> p_t fp16 (coalesced via smem stage) + tile stats
// MODE 4: normalize + PV -> att fp32 (stcs) + fp16 ctx
//         (rowstat computed inline from stats)
// MODE 5: merged QKV proj -> q/k fp16 scatter [bh,s,d], v fp16 [bh,d,s]
// ============================================================
template <int BN, int MODE, int SPLIT, int NSTG, int MAXB, typename T>
__global__ __launch_bounds__(256, MAXB)
void mma_gemm(const T* __restrict__ Ah_g, const T* __restrict__ Al_g,
              const void* __restrict__ Aux_g,
              const T* __restrict__ Bh_g, const T* __restrict__ Bl_g,
              const float* __restrict__ bias, const int* __restrict__ mask,
              float* __restrict__ outf, uint32_t* __restrict__ ohi,
              uint32_t* __restrict__ olo, uint32_t* __restrict__ ov,
              float2* __restrict__ stats,
              const T* __restrict__ Ak_g, const T* __restrict__ Av_g,
              int K, size_t sAz, size_t sBz)
{
    constexpr bool BF16 = is_same_t<T, __nv_bfloat16>::v;
    constexpr int BM = 128, BK = 32;
    constexpr int ASZ = BM * 80;
    constexpr int BSZ = BN * 80;
    constexpr int BPART = (SPLIT >= 2) ? 2 : 1;
    constexpr int OFF_BH = ASZ;
    constexpr int STG = ASZ + BSZ * BPART;
    constexpr int NSPAN = BN / 2;
    constexpr int NT = NSPAN / 8;

    extern __shared__ char smem[];
    const uint32_t sb = smem_u32(smem);
    const int tid = threadIdx.x;
    const int lane = tid & 31, wid = tid >> 5;
    const int wm = wid & 3, wn = wid >> 2;

    const int m0 = blockIdx.y * BM;
    const int n0 = blockIdx.x * BN;
    const int z  = blockIdx.z;
    const int sec = (MODE == 5) ? (n0 >> 10) : 0;

    const T* pAh = Ah_g ? Ah_g + (size_t)z * sAz : nullptr;
    if (MODE == 5) pAh = (sec == 0) ? Ah_g : (sec == 1) ? Ak_g : Av_g;
    const __half* pPt = (MODE == 4) ? (const __half*)Aux_g + (size_t)z * sAz : nullptr;
    float* pW = (MODE == 4) ? outf + (size_t)z * sAz : nullptr;
    const T* pBh = Bh_g + (size_t)z * sBz;
    const T* pBl = Bl_g ? Bl_g + (size_t)z * sBz : nullptr;

    const int NCH = K / BK;

    // MODE 4: per-row (max, invS) computed inline from per-tile stats
    float2 rs[4];
    float sc[4];
    int cur_t = -1;
    if (MODE == 4) {
#pragma unroll
        for (int j = 0; j < 4; j++) {
            const int row = m0 + (tid >> 3) + j * 32;
            float M = -1e30f;
            for (int kb = 0; kb < 16; kb++)
                M = fmaxf(M, stats[((size_t)z * 16 + kb) * SQ + row].x);
            float S = 0.0f;
            for (int kb = 0; kb < 16; kb++) {
                const float2 t = stats[((size_t)z * 16 + kb) * SQ + row];
                S += t.y * __expf(t.x - M);
            }
            rs[j] = make_float2(M, 1.0f / S);
        }
    }

    auto issue = [&](int c, int st) {
        const int kb = c * BK;
        const uint32_t base = sb + st * STG;
        if (MODE != 4) {
#pragma unroll
            for (int j = 0; j < 2; j++) {
                int u = tid + j * 256, r = u >> 2, c8 = u & 3;
                cpa16(base + r * 80 + c8 * 16,
                      pAh + (size_t)(m0 + r) * K + kb + c8 * 8);
            }
        }
#pragma unroll
        for (int j = 0; j < (BN == 128 ? 2 : 1); j++) {
            int u = tid + j * 256, r = u >> 2, c8 = u & 3;
            cpa16(base + OFF_BH + r * 80 + c8 * 16,
                  pBh + (size_t)(n0 + r) * K + kb + c8 * 8);
            if (SPLIT >= 2)
                cpa16(base + OFF_BH + BSZ + r * 80 + c8 * 16,
                      pBl + (size_t)(n0 + r) * K + kb + c8 * 8);
        }
    };

    // ----- MODE 4: p_t fp16 loads + scale + att write + fp16 smem store -----
    uint2 rAp[4];
    auto loadA = [&](int c) {
        const int kb = c * BK;
#pragma unroll
        for (int j = 0; j < 4; j++) {
            int u = tid + j * 256, r = u >> 3, c4 = u & 7;
            rAp[j] = *(const uint2*)(pPt + (size_t)(m0 + r) * K + kb + c4 * 4);
        }
    };
    auto storeA = [&](int c) {
        const int st = c % NSTG, kb = c * BK;
        char* base = smem + st * STG;
        const int t = c >> 2;
        if (t != cur_t) {
            cur_t = t;
#pragma unroll
            for (int j = 0; j < 4; j++) {
                const int r = (tid >> 3) + j * 32;
                const float Mt = stats[((size_t)z * 16 + t) * SQ + m0 + r].x;
                sc[j] = __expf(Mt - rs[j].x) * rs[j].y;
            }
        }
#pragma unroll
        for (int j = 0; j < 4; j++) {
            int u = tid + j * 256, r = u >> 3, c4 = u & 7;
            __half2 h01 = *(__half2*)&rAp[j].x;
            __half2 h23 = *(__half2*)&rAp[j].y;
            float4 p;
            p.x = __low2float(h01)  * sc[j];
            p.y = __high2float(h01) * sc[j];
            p.z = __low2float(h23)  * sc[j];
            p.w = __high2float(h23) * sc[j];
            __stcs((float4*)(pW + (size_t)(m0 + r) * K + kb + c4 * 4), p);
            __half2 o0 = __floats2half2_rn(p.x, p.y);
            __half2 o1 = __floats2half2_rn(p.z, p.w);
            *(int2*)(base + r * 80 + c4 * 8) = make_int2(*(int*)&o0, *(int*)&o1);
        }
    };

    float acc[2][NT][4];
#pragma unroll
    for (int a = 0; a < 2; a++)
#pragma unroll
        for (int b = 0; b < NT; b++)
#pragma unroll
            for (int c = 0; c < 4; c++) acc[a][b][c] = 0.0f;

#pragma unroll
    for (int s = 0; s < NSTG - 1; s++) {
        if (s < NCH) issue(s, s);
        cpa_commit();
    }
    if (MODE == 4) { loadA(0); storeA(0); }

    for (int c = 0; c < NCH; c++) {
        const int st = c % NSTG;
        cpa_waitg<NSTG - 2>();
        __syncthreads();
        if (c + NSTG - 1 < NCH) issue(c + NSTG - 1, (c + NSTG - 1) % NSTG);
        cpa_commit();
        if (MODE == 4 && c + 1 < NCH) loadA(c + 1);

        const uint32_t aBase = sb + st * STG;
        const uint32_t bBase = aBase + OFF_BH;
#pragma unroll
        for (int ks = 0; ks < 2; ks++) {
            uint32_t ah[2][4];
#pragma unroll
            for (int mt = 0; mt < 2; mt++) {
                uint32_t ad = aBase + (wm * 32 + mt * 16 + (lane & 15)) * 80
                              + ks * 32 + ((lane >> 4) << 4);
                ldm4(ah[mt], ad);
            }
            const int g = lane >> 3;
            const int nsub = (g >> 1) * 8, khalf = (g & 1) * 16;
#pragma unroll
            for (int ntp = 0; ntp < NT / 2; ntp++) {
                uint32_t bd = bBase
                    + (wn * NSPAN + ntp * 16 + nsub + (lane & 7)) * 80
                    + ks * 32 + khalf;
                uint32_t bh[4];
                ldm4(bh, bd);
#pragma unroll
                for (int mt = 0; mt < 2; mt++) {
                    mma16816<BF16>(acc[mt][2 * ntp],     ah[mt], bh[0], bh[1]);
                    mma16816<BF16>(acc[mt][2 * ntp + 1], ah[mt], bh[2], bh[3]);
                }
                if (SPLIT >= 2) {
                    uint32_t bl[4];
                    ldm4(bl, bd + BSZ);
#pragma unroll
                    for (int mt = 0; mt < 2; mt++) {
                        mma16816<BF16>(acc[mt][2 * ntp],     ah[mt], bl[0], bl[1]);
                        mma16816<BF16>(acc[mt][2 * ntp + 1], ah[mt], bl[2], bl[3]);
                    }
                }
            }
        }
        if (MODE == 4 && c + 1 < NCH) storeA(c + 1);
    }
    __syncthreads();

    // ---------------- epilogue ----------------
    float (*sf)[BN + 1] = (float(*)[BN + 1])smem;  // MODE5-V staging

#pragma unroll
    for (int mt = 0; mt < 2; mt++)
#pragma unroll
        for (int nt = 0; nt < NT; nt++)
#pragma unroll
            for (int hh = 0; hh < 2; hh++) {
                float v0 = acc[mt][nt][hh * 2 + 0];
                float v1 = acc[mt][nt][hh * 2 + 1];
                const int m_loc = wm * 32 + mt * 16 + (lane >> 2) + hh * 8;
                const int n_loc = wn * NSPAN + nt * 8 + (lane & 3) * 2;
                const int gm = m0 + m_loc, gn = n0 + n_loc;

                if (MODE == 2) {
                    v0 += bias[gn]; v1 += bias[gn + 1];
                    *(float2*)&outf[(size_t)gm * DM + gn] = make_float2(v0, v1);
                } else if (MODE == 3) {
                    v0 *= 0.125f; v1 *= 0.125f;
                    const size_t midx = ((size_t)(z >> 4) * SQ + gm) * SQ + gn;
                    int2 mv = *(const int2*)(mask + midx);
                    if (mv.x == 0) v0 = 1e-9f;
                    if (mv.y == 0) v1 = 1e-9f;
                    acc[mt][nt][hh * 2 + 0] = v0;
                    acc[mt][nt][hh * 2 + 1] = v1;
                } else if (MODE == 4) {
                    const int b = z >> 4, h = z & 15;
                    const size_t a = (((size_t)(b * SQ + gm)) * DM + h * DKH + gn) >> 1;
                    ohi[a] = pack_hf2(v0, v1);
                } else if (MODE == 5) {
                    v0 += bias[gn]; v1 += bias[gn + 1];
                    if (sec < 2) {
                        const int gnl = gn & 1023;
                        const int b = gm >> 11, s = gm & 2047, h = gnl >> 6, d = gnl & 63;
                        const size_t a = ((((size_t)(b * NH + h)) * SQ + s) * DKH + d) >> 1;
                        (sec ? olo : ohi)[a] = pack_hf2(v0, v1);
                    } else {
                        sf[m_loc][n_loc]     = v0;
                        sf[m_loc][n_loc + 1] = v1;
                    }
                }
            }

    if (MODE == 5 && sec == 2) {                   // V transpose -> [bh, d, s]
        __syncthreads();
        const int b = m0 >> 11, s0 = m0 & 2047;
        const int gnl_base = n0 & 1023;
#pragma unroll
        for (int it = 0; it < BN / 8; it++) {
            const int rn = it * 8 + wid;
            const int gnl = gnl_base + rn;
            const int h = gnl >> 6, d = gnl & 63;
            uint32_t* orow = ov + ((((size_t)(b * NH + h)) * DKH + d) * SQ + s0) / 2;
#pragma unroll
            for (int j = 0; j < 2; j++) {
                const int sp = j * 64 + 2 * lane;
                orow[j * 32 + lane] = pack_hf2(sf[sp][rn], sf[sp + 1][rn]);
            }
        }
    }

    if (MODE == 3) {
        float* smax = (float*)smem;                       // [2][128]
        float* ssum = smax + 256;
        __half (*stg)[136] = (__half(*)[136])(smem + 2048); // 128 x 136 halves
        // phase 1: per-half row max
#pragma unroll
        for (int mt = 0; mt < 2; mt++)
#pragma unroll
            for (int hh = 0; hh < 2; hh++) {
                float mx = -1e30f;
#pragma unroll
                for (int nt = 0; nt < NT; nt++)
                    mx = fmaxf(mx, fmaxf(acc[mt][nt][hh * 2], acc[mt][nt][hh * 2 + 1]));
                mx = fmaxf(mx, __shfl_xor_sync(0xffffffffu, mx, 1));
                mx = fmaxf(mx, __shfl_xor_sync(0xffffffffu, mx, 2));
                if ((lane & 3) == 0)
                    smax[wn * 128 + wm * 32 + mt * 16 + hh * 8 + (lane >> 2)] = mx;
            }
        __syncthreads();
        // phase 2: combined max -> p_t into smem stage + sums
#pragma unroll
        for (int mt = 0; mt < 2; mt++)
#pragma unroll
            for (int hh = 0; hh < 2; hh++) {
                const int m_loc = wm * 32 + mt * 16 + hh * 8 + (lane >> 2);
                const float mx = fmaxf(smax[m_loc], smax[128 + m_loc]);
                float sm = 0.0f;
#pragma unroll
                for (int nt = 0; nt < NT; nt++) {
                    const float e0 = __expf(acc[mt][nt][hh * 2 + 0] - mx);
                    const float e1 = __expf(acc[mt][nt][hh * 2 + 1] - mx);
                    sm += e0 + e1;
                    const int n_loc = wn * NSPAN + nt * 8 + (lane & 3) * 2;
                    *(uint32_t*)&stg[m_loc][n_loc] = pack_hf2(e0, e1);
                }
                sm += __shfl_xor_sync(0xffffffffu, sm, 1);
                sm += __shfl_xor_sync(0xffffffffu, sm, 2);
                if ((lane & 3) == 0) ssum[wn * 128 + m_loc] = sm;
            }
        __syncthreads();
        if (tid < 128) {
            stats[((size_t)z * 16 + blockIdx.x) * SQ + m0 + tid] =
                make_float2(fmaxf(smax[tid], smax[128 + tid]),
                            ssum[tid] + ssum[128 + tid]);
        }
        // coalesced p_t copy: 128 rows x 128 halves, 16B/lane streaming
        __half* pPtOut = (__half*)ohi;
#pragma unroll
        for (int it = 0; it < 8; it++) {
            const int u = tid + it * 256;
            const int r = u >> 4, c8 = u & 15;
            int4 val = *(int4*)&stg[r][c8 * 8];
            __stcs((int4*)(pPtOut + ((size_t)z * SQ + m0 + r) * SQ + n0 + c8 * 8), val);
        }
    }
}

// ---------------- all conversions in ONE launch ----------------
__device__ __forceinline__ void cvt4(const float* __restrict__ x,
                                     __half* __restrict__ o, size_t j)
{
    float4 v = ((const float4*)x)[j];
    __half2 h0 = __floats2half2_rn(v.x, v.y);
    __half2 h1 = __floats2half2_rn(v.z, v.w);
    ((int2*)o)[j] = make_int2(*(int*)&h0, *(int*)&h1);
}

__global__ __launch_bounds__(256)
void cvt_all(const float* __restrict__ q, const float* __restrict__ k,
             const float* __restrict__ v,
             const float* __restrict__ Wq, const float* __restrict__ Wk,
             const float* __restrict__ Wv, const float* __restrict__ Wo,
             const float* __restrict__ bq, const float* __restrict__ bk,
             const float* __restrict__ bv,
             __half* __restrict__ xq, __half* __restrict__ xk,
             __half* __restrict__ xv, __half* __restrict__ wqkv,
             __half* __restrict__ wo, float* __restrict__ bqkv)
{
    const size_t n4x = XN / 4, n4w = WN / 4;
    size_t i = (size_t)blockIdx.x * 256 + threadIdx.x;
    if (i < 3 * n4x) {
        const int sel = (int)(i / n4x);
        const size_t j = i - (size_t)sel * n4x;
        cvt4(sel == 0 ? q : sel == 1 ? k : v,
             sel == 0 ? xq : sel == 1 ? xk : xv, j);
    } else if (i < 3 * n4x + 3 * n4w) {
        const size_t t = i - 3 * n4x;
        const int sel = (int)(t / n4w);
        const size_t j = t - (size_t)sel * n4w;
        cvt4(sel == 0 ? Wq : sel == 1 ? Wk : Wv, wqkv + (size_t)sel * WN, j);
    } else if (i < 3 * n4x + 4 * n4w) {
        cvt4(Wo, wo, i - 3 * n4x - 3 * n4w);
    } else {
        const size_t j = i - 3 * n4x - 4 * n4w;   // 0..767, 4 bias elems each
        if (j < 3 * DM / 4) {
#pragma unroll
            for (int e = 0; e < 4; e++) {
                const int idx = (int)j * 4 + e;
                bqkv[idx] = (idx < DM) ? bq[idx]
                          : (idx < 2 * DM) ? bk[idx - DM] : bv[idx - 2 * DM];
            }
        }
    }
}

// ============================================================
extern "C" void kernel_launch(void* const* d_in, const int* in_sizes, int n_in,
                              void* d_out, int out_size)
{
    const float* q    = (const float*)d_in[0];
    const float* k    = (const float*)d_in[1];
    const float* v    = (const float*)d_in[2];
    const int*   mask = (const int*)  d_in[3];
    const float* Wq   = (const float*)d_in[4];
    const float* bq   = (const float*)d_in[5];
    const float* Wk   = (const float*)d_in[6];
    const float* bk   = (const float*)d_in[7];
    const float* Wv   = (const float*)d_in[8];
    const float* bv   = (const float*)d_in[9];
    const float* Wo   = (const float*)d_in[10];
    const float* bo   = (const float*)d_in[11];

    __half *xq, *xk, *xv, *wqkv, *qh, *kh, *vt, *pt, *ctx, *wo;
    float *bqkv;
    float *attscr, *dummy;
    float2 *statsp;
    cudaGetSymbolAddress((void**)&xq, g_xq); cudaGetSymbolAddress((void**)&xk, g_xk);
    cudaGetSymbolAddress((void**)&xv, g_xv);
    cudaGetSymbolAddress((void**)&wqkv, g_wqkv);
    cudaGetSymbolAddress((void**)&bqkv, g_bqkv);
    cudaGetSymbolAddress((void**)&wo, g_wo);
    cudaGetSymbolAddress((void**)&qh, g_qh); cudaGetSymbolAddress((void**)&kh, g_kh);
    cudaGetSymbolAddress((void**)&vt, g_vt);
    cudaGetSymbolAddress((void**)&pt, g_pt);
    cudaGetSymbolAddress((void**)&ctx, g_ctx);
    cudaGetSymbolAddress((void**)&attscr, g_att_scratch);
    cudaGetSymbolAddress((void**)&dummy,  g_dummy_out);
    cudaGetSymbolAddress((void**)&statsp, g_stats);

    const long OUT_ELEMS = (long)NB * SQ * DM;
    const long ATT_ELEMS = (long)AN;
    float* outp = (float*)d_out;
    float* attp;
    if ((long)out_size >= OUT_ELEMS + ATT_ELEMS)      attp = outp + OUT_ELEMS;
    else if ((long)out_size == ATT_ELEMS) { attp = outp; outp = dummy; }
    else                                               attp = attscr;

    constexpr int SM_P1_128 = 3 * (10240 + 10240);          // 61440
    constexpr int SM_PROJ   = 66048;                         // max(61440, 128*129*4 staging)
    constexpr int SM_PV4    = 4 * (10240 + 5120);            // 61440 (4-stage PV)
    constexpr int SM_OUT    = 3 * (10240 + 10240);           // 61440 (single-split out proj)

    cudaFuncSetAttribute(mma_gemm<128, 5, 1, 3, 2, __half>,
                         cudaFuncAttributeMaxDynamicSharedMemorySize, SM_PROJ);
    cudaFuncSetAttribute(mma_gemm<128, 3, 1, 3, 2, __half>,
                         cudaFuncAttributeMaxDynamicSharedMemorySize, SM_P1_128);
    cudaFuncSetAttribute(mma_gemm<64, 4, 1, 4, 2, __half>,
                         cudaFuncAttributeMaxDynamicSharedMemorySize, SM_PV4);
    cudaFuncSetAttribute(mma_gemm<128, 2, 1, 3, 2, __half>,
                         cudaFuncAttributeMaxDynamicSharedMemorySize, SM_OUT);

    // all conversions + bias concat in one launch
    {
        const size_t total = 3 * (XN / 4) + 4 * (WN / 4) + 3 * DM / 4;
        cvt_all<<<(int)((total + 255) / 256), 256>>>(
            q, k, v, Wq, Wk, Wv, Wo, bq, bk, bv,
            xq, xk, xv, wqkv, wo, bqkv);
    }

    // merged QKV projection (M=4096, N=3072, K=1024), BN=128, 2 CTAs/SM
    mma_gemm<128, 5, 1, 3, 2, __half><<<dim3(24, 32, 1), 256, SM_PROJ>>>(
        xq, nullptr, nullptr, wqkv, nullptr, bqkv, nullptr, nullptr,
        (uint32_t*)qh, (uint32_t*)kh, (uint32_t*)vt, nullptr,
        xk, xv, DM, 0, 0);

    // scores: p_t fp16 (coalesced) + per-tile row stats
    mma_gemm<128, 3, 1, 3, 2, __half><<<dim3(16, 16, NBH), 256, SM_P1_128>>>(
        qh, nullptr, nullptr, kh, nullptr, nullptr, mask, nullptr,
        (uint32_t*)pt, nullptr, nullptr, statsp,
        nullptr, nullptr, DKH, (size_t)SQ * DKH, (size_t)SQ * DKH);

    // normalize + PV: 4-stage pipeline
    mma_gemm<64, 4, 1, 4, 2, __half><<<dim3(1, 16, NBH), 256, SM_PV4>>>(
        nullptr, nullptr, pt, vt, nullptr, nullptr, nullptr, attp,
        (uint32_t*)ctx, nullptr, nullptr, statsp,
        nullptr, nullptr, SQ, (size_t)SQ * SQ, (size_t)DKH * SQ);

    // output projection: fp16 ctx x fp16 Wo, single MMA
    mma_gemm<128, 2, 1, 3, 2, __half><<<dim3(8, 32, 1), 256, SM_OUT>>>(
        ctx, nullptr, nullptr, wo, nullptr, bo, nullptr, outp,
        nullptr, nullptr, nullptr, nullptr,
        nullptr, nullptr, DM, 0, 0);
}